// round 8
// baseline (speedup 1.0000x reference)
#include <cuda_runtime.h>
#include <math.h>

// Problem constants
#define Sv   512
#define Bv   64
#define FINv 512
#define Hv   512
#define G4   2048   // 4*H

__device__ float g_gx[(size_t)Sv * Bv * G4];

// Grid-barrier state (generation-based; leftovers across replays harmless).
__device__ unsigned int g_count = 0;
__device__ unsigned int g_gen   = 0;

#define NBLK 128

__device__ __forceinline__ unsigned cvt_tf32(float x) {
    unsigned u;
    asm("cvt.rna.tf32.f32 %0, %1;" : "=r"(u) : "f"(x));
    return u;
}

__device__ __forceinline__ void mma_tf32(float c[4], const unsigned a[4],
                                         const unsigned b[2]) {
    asm("mma.sync.aligned.m16n8k8.row.col.f32.tf32.tf32.f32 "
        "{%0,%1,%2,%3}, {%4,%5,%6,%7}, {%8,%9}, {%0,%1,%2,%3};"
        : "+f"(c[0]), "+f"(c[1]), "+f"(c[2]), "+f"(c[3])
        : "r"(a[0]), "r"(a[1]), "r"(a[2]), "r"(a[3]),
          "r"(b[0]), "r"(b[1]));
}

// ===========================================================================
// Phase 1: gx = X[32768,512] @ W_ih^T[512,2048] + (b_ih + b_hh)
// tf32 mma.m16n8k8, 128x128 block tile, 8 warps, 64x32 warp tile. (R6, kept.)
// ===========================================================================
#define P1ROW 36

__global__ __launch_bounds__(256, 2) void gemm_x_tf32(
    const float* __restrict__ X,
    const float* __restrict__ W,
    const float* __restrict__ bih,
    const float* __restrict__ bhh)
{
    __shared__ unsigned As[128 * P1ROW];
    __shared__ unsigned Bs[128 * P1ROW];

    const int tid  = threadIdx.x;
    const int wid  = tid >> 5;
    const int lane = tid & 31;
    const int g    = lane >> 2;
    const int t    = lane & 3;

    const int m0 = blockIdx.y * 128;
    const int n0 = blockIdx.x * 128;
    const int wm = (wid >> 2) * 64;
    const int wn = (wid & 3) * 32;

    const int lr  = tid >> 3;
    const int lc4 = (tid & 7) * 4;

    float acc[4][4][4];
#pragma unroll
    for (int mi = 0; mi < 4; mi++)
#pragma unroll
        for (int nj = 0; nj < 4; nj++)
#pragma unroll
            for (int q = 0; q < 4; q++) acc[mi][nj][q] = 0.f;

    for (int k0 = 0; k0 < FINv; k0 += 32) {
#pragma unroll
        for (int rr = 0; rr < 128; rr += 32) {
            int row = lr + rr;
            float4 av = *reinterpret_cast<const float4*>(
                X + (size_t)(m0 + row) * FINv + k0 + lc4);
            uint4 at = make_uint4(cvt_tf32(av.x), cvt_tf32(av.y),
                                  cvt_tf32(av.z), cvt_tf32(av.w));
            *reinterpret_cast<uint4*>(&As[row * P1ROW + lc4]) = at;
            float4 bv = *reinterpret_cast<const float4*>(
                W + (size_t)(n0 + row) * FINv + k0 + lc4);
            uint4 bt = make_uint4(cvt_tf32(bv.x), cvt_tf32(bv.y),
                                  cvt_tf32(bv.z), cvt_tf32(bv.w));
            *reinterpret_cast<uint4*>(&Bs[row * P1ROW + lc4]) = bt;
        }
        __syncthreads();

#pragma unroll
        for (int kk = 0; kk < 32; kk += 8) {
            unsigned afr[4][4], bfr[4][2];
#pragma unroll
            for (int mi = 0; mi < 4; mi++) {
                int base = (wm + mi * 16 + g) * P1ROW + kk + t;
                afr[mi][0] = As[base];
                afr[mi][1] = As[base + 8 * P1ROW];
                afr[mi][2] = As[base + 4];
                afr[mi][3] = As[base + 8 * P1ROW + 4];
            }
#pragma unroll
            for (int nj = 0; nj < 4; nj++) {
                int bb = (wn + nj * 8 + g) * P1ROW + kk + t;
                bfr[nj][0] = Bs[bb];
                bfr[nj][1] = Bs[bb + 4];
            }
#pragma unroll
            for (int mi = 0; mi < 4; mi++)
#pragma unroll
                for (int nj = 0; nj < 4; nj++)
                    mma_tf32(acc[mi][nj], afr[mi], bfr[nj]);
        }
        __syncthreads();
    }

#pragma unroll
    for (int nj = 0; nj < 4; nj++) {
        int n = n0 + wn + nj * 8 + 2 * t;
        float bs0 = bih[n] + bhh[n];
        float bs1 = bih[n + 1] + bhh[n + 1];
#pragma unroll
        for (int mi = 0; mi < 4; mi++) {
            int row = m0 + wm + mi * 16 + g;
            float2 v0 = make_float2(acc[mi][nj][0] + bs0, acc[mi][nj][1] + bs1);
            float2 v1 = make_float2(acc[mi][nj][2] + bs0, acc[mi][nj][3] + bs1);
            *reinterpret_cast<float2*>(&g_gx[(size_t)row * G4 + n])       = v0;
            *reinterpret_cast<float2*>(&g_gx[(size_t)(row + 8) * G4 + n]) = v1;
        }
    }
}

// ===========================================================================
// Phase 2: persistent recurrence, tensor-core mainloop.
// 128 blocks x 128 threads. Block bx owns hidden units [4bx,4bx+4) = 16 cols.
// W_hh held in smem as a 2-term tf32 split (W1+W2, exact to fp32); h split
// per-element at fragment load. Warp w computes batches [16w,16w+16) x 16
// cols via m16n8k8: acc = gx + W1*h1 + W1*h2 + W2*h1  (fp32 accumulate).
// c(t-1) in registers; single-flag generation barrier between steps.
// ===========================================================================
#define HPAD 516                       // fp32 h rows (conflict-free: 4g+t mod 32)
#define WPAD 516
#define W1_OFF 0
#define W2_OFF (16 * WPAD)
#define H_OFF  (32 * WPAD)
#define EX_OFF (H_OFF + 64 * HPAD)
#define SM2_FLOATS (EX_OFF + 16 * 68)   // 50624 floats = 202496 B

__global__ __launch_bounds__(128, 1) void lstm_rec_kernel(
    const float* __restrict__ whh,   // [2048][512]
    float* __restrict__ out)
{
    extern __shared__ float sm[];
    unsigned* w1_s = reinterpret_cast<unsigned*>(sm + W1_OFF);  // [16][WPAD]
    unsigned* w2_s = reinterpret_cast<unsigned*>(sm + W2_OFF);  // [16][WPAD]
    float*    h_s  = sm + H_OFF;                                 // [64][HPAD]
    float*    ex   = sm + EX_OFF;                                // [16][68]

    float* hs_out = out;
    float* cs_out = out + (size_t)Sv * Bv * Hv;

    const int tid  = threadIdx.x;
    const int wid  = tid >> 5;
    const int lane = tid & 31;
    const int g    = lane >> 2;
    const int t    = lane & 3;
    const int u0   = blockIdx.x * 4;
    const int wbat = wid * 16;           // warp's batch base

    // W_hh split into (W1, W2) tf32 pair, once.
    for (int i = tid; i < 16 * Hv; i += 128) {
        int c = i >> 9, k = i & (Hv - 1);
        int gr = ((c >> 2) * Hv) + u0 + (c & 3);
        float w = whh[(size_t)gr * Hv + k];
        unsigned w1 = cvt_tf32(w);
        w1_s[c * WPAD + k] = w1;
        w2_s[c * WPAD + k] = cvt_tf32(w - __uint_as_float(w1));
    }

    unsigned bar_base = 0;
    if (tid == 0) bar_base = atomicAdd(&g_gen, 0u);

    // gx/epilogue column mapping: local col c -> global gate col
    //   gate = c>>2, unit = c&3  ->  gcol = (c>>2)*Hv + u0 + (c&3)
    int gcol[2];                          // for cols nj*8 + 2t (pairs 2t,2t+1 adjacent)
#pragma unroll
    for (int nj = 0; nj < 2; nj++) {
        int c = nj * 8 + 2 * t;
        gcol[nj] = ((c >> 2) * Hv) + u0 + (c & 3);
    }

    // Elementwise mapping: items tid*2+r -> fixed (u,b); c in registers.
    float cpv[2] = {0.f, 0.f};

    __syncthreads();

    for (int t_s = 0; t_s < Sv; t_s++) {
        // ---- stage h(t-1) into smem (fp32) ----
        if (t_s == 0) {
            for (int i = tid; i < 64 * HPAD; i += 128) h_s[i] = 0.f;
        } else {
            const float* hp = hs_out + (size_t)(t_s - 1) * Bv * Hv;
#pragma unroll 16
            for (int j = 0; j < 64; j++) {
                float4 v = __ldcg(reinterpret_cast<const float4*>(hp + (size_t)j * Hv) + tid);
                *reinterpret_cast<float4*>(h_s + (size_t)j * HPAD + 4 * tid) = v;
            }
        }

        // ---- init accumulators from gx (bias already folded in phase 1) ----
        float acc[2][4];
        {
            const float* gxt = g_gx + (size_t)t_s * (Bv * G4);
#pragma unroll
            for (int nj = 0; nj < 2; nj++) {
                float2 lo = *reinterpret_cast<const float2*>(
                    gxt + (size_t)(wbat + g) * G4 + gcol[nj]);
                float2 hi = *reinterpret_cast<const float2*>(
                    gxt + (size_t)(wbat + g + 8) * G4 + gcol[nj]);
                acc[nj][0] = lo.x; acc[nj][1] = lo.y;
                acc[nj][2] = hi.x; acc[nj][3] = hi.y;
            }
        }
        __syncthreads();

        // ---- tensor-core recurrent GEMM, exact-fp32 via 2-term split ----
        const int r0 = (wbat + g) * HPAD + t;
        const int r1 = (wbat + g + 8) * HPAD + t;
#pragma unroll 4
        for (int kt = 0; kt < 64; kt++) {
            int k0 = kt * 8;
            float h0 = h_s[r0 + k0];
            float h1 = h_s[r1 + k0];
            float h2 = h_s[r0 + k0 + 4];
            float h3 = h_s[r1 + k0 + 4];
            unsigned a1[4], a2[4];
            a1[0] = cvt_tf32(h0); a2[0] = cvt_tf32(h0 - __uint_as_float(a1[0]));
            a1[1] = cvt_tf32(h1); a2[1] = cvt_tf32(h1 - __uint_as_float(a1[1]));
            a1[2] = cvt_tf32(h2); a2[2] = cvt_tf32(h2 - __uint_as_float(a1[2]));
            a1[3] = cvt_tf32(h3); a2[3] = cvt_tf32(h3 - __uint_as_float(a1[3]));
#pragma unroll
            for (int nj = 0; nj < 2; nj++) {
                int wb = (nj * 8 + g) * WPAD + k0 + t;
                unsigned b1[2], b2[2];
                b1[0] = w1_s[wb]; b1[1] = w1_s[wb + 4];
                b2[0] = w2_s[wb]; b2[1] = w2_s[wb + 4];
                mma_tf32(acc[nj], a1, b1);   // W1*h1
                mma_tf32(acc[nj], a2, b1);   // W1*h2
                mma_tf32(acc[nj], a1, b2);   // W2*h1
            }
        }

        // ---- exchange gate pre-activations ----
#pragma unroll
        for (int nj = 0; nj < 2; nj++) {
            int c = nj * 8 + 2 * t;
            ex[c * 68 + wbat + g]           = acc[nj][0];
            ex[(c + 1) * 68 + wbat + g]     = acc[nj][1];
            ex[c * 68 + wbat + g + 8]       = acc[nj][2];
            ex[(c + 1) * 68 + wbat + g + 8] = acc[nj][3];
        }
        __syncthreads();

        // ---- LSTM update: 2 (unit,batch) items per thread, c in regs ----
        float* ht = hs_out + (size_t)t_s * Bv * Hv;
        float* ct = cs_out + (size_t)t_s * Bv * Hv;
#pragma unroll
        for (int r = 0; r < 2; r++) {
            int item = tid * 2 + r;
            int u = item >> 6, b = item & 63;
            float gi = ex[(0 + u)  * 68 + b];
            float gf = ex[(4 + u)  * 68 + b];
            float gg = ex[(8 + u)  * 68 + b];
            float go = ex[(12 + u) * 68 + b];
            float si = 1.f / (1.f + expf(-gi));
            float sf = 1.f / (1.f + expf(-gf));
            float so = 1.f / (1.f + expf(-go));
            float tg = tanhf(gg);
            float cc = sf * cpv[r] + si * tg;
            cpv[r] = cc;
            float hh = so * tanhf(cc);
            __stcg(ht + (size_t)b * Hv + u0 + u, hh);
            __stcg(ct + (size_t)b * Hv + u0 + u, cc);
        }

        // ---- grid barrier between steps ----
        if (t_s < Sv - 1) {
            __threadfence();
            __syncthreads();
            if (tid == 0) {
                unsigned target = bar_base + (unsigned)t_s + 1u;
                if (atomicAdd(&g_count, 1u) == NBLK - 1u) {
                    atomicExch(&g_count, 0u);
                    __threadfence();
                    atomicExch(&g_gen, target);
                } else {
                    while ((int)(atomicAdd(&g_gen, 0u) - target) < 0) { }
                }
                __threadfence();
            }
            __syncthreads();
        }
    }
}

// ===========================================================================
// Launch
// ===========================================================================
extern "C" void kernel_launch(void* const* d_in, const int* in_sizes, int n_in,
                              void* d_out, int out_size)
{
    const float* seq  = (const float*)d_in[0];
    const float* w_ih = (const float*)d_in[1];
    const float* w_hh = (const float*)d_in[2];
    const float* b_ih = (const float*)d_in[3];
    const float* b_hh = (const float*)d_in[4];
    float* out = (float*)d_out;

    const int smem_p2 = SM2_FLOATS * (int)sizeof(float);   // 202496 B
    cudaFuncSetAttribute(lstm_rec_kernel,
                         cudaFuncAttributeMaxDynamicSharedMemorySize, smem_p2);

    dim3 g1(G4 / 128, (Sv * Bv) / 128);   // (16, 256)
    gemm_x_tf32<<<g1, 256>>>(seq, w_ih, b_ih, b_hh);
    lstm_rec_kernel<<<NBLK, 128, smem_p2>>>(w_hh, out);
}

// round 9
// speedup vs baseline: 1.4662x; 1.4662x over previous
#include <cuda_runtime.h>
#include <math.h>

// Problem constants
#define Sv   512
#define Bv   64
#define FINv 512
#define Hv   512
#define G4   2048   // 4*H

__device__ float g_gx[(size_t)Sv * Bv * G4];

// Grid-barrier state (generation-based; leftovers across replays harmless).
__device__ unsigned int g_count = 0;
__device__ unsigned int g_gen   = 0;

#define NBLK 128

__device__ __forceinline__ unsigned cvt_tf32(float x) {
    unsigned u;
    asm("cvt.rna.tf32.f32 %0, %1;" : "=r"(u) : "f"(x));
    return u;
}

__device__ __forceinline__ void mma_tf32(float c[4], const unsigned a[4],
                                         const unsigned b[2]) {
    asm("mma.sync.aligned.m16n8k8.row.col.f32.tf32.tf32.f32 "
        "{%0,%1,%2,%3}, {%4,%5,%6,%7}, {%8,%9}, {%0,%1,%2,%3};"
        : "+f"(c[0]), "+f"(c[1]), "+f"(c[2]), "+f"(c[3])
        : "r"(a[0]), "r"(a[1]), "r"(a[2]), "r"(a[3]),
          "r"(b[0]), "r"(b[1]));
}

// ===========================================================================
// Phase 1: gx = X[32768,512] @ W_ih^T[512,2048] + (b_ih + b_hh)
// tf32 mma.m16n8k8, 128x128 block tile, 8 warps, 64x32 warp tile. (R6, kept.)
// ===========================================================================
#define P1ROW 36

__global__ __launch_bounds__(256, 2) void gemm_x_tf32(
    const float* __restrict__ X,
    const float* __restrict__ W,
    const float* __restrict__ bih,
    const float* __restrict__ bhh)
{
    __shared__ unsigned As[128 * P1ROW];
    __shared__ unsigned Bs[128 * P1ROW];

    const int tid  = threadIdx.x;
    const int wid  = tid >> 5;
    const int lane = tid & 31;
    const int g    = lane >> 2;
    const int t    = lane & 3;

    const int m0 = blockIdx.y * 128;
    const int n0 = blockIdx.x * 128;
    const int wm = (wid >> 2) * 64;
    const int wn = (wid & 3) * 32;

    const int lr  = tid >> 3;
    const int lc4 = (tid & 7) * 4;

    float acc[4][4][4];
#pragma unroll
    for (int mi = 0; mi < 4; mi++)
#pragma unroll
        for (int nj = 0; nj < 4; nj++)
#pragma unroll
            for (int q = 0; q < 4; q++) acc[mi][nj][q] = 0.f;

    for (int k0 = 0; k0 < FINv; k0 += 32) {
#pragma unroll
        for (int rr = 0; rr < 128; rr += 32) {
            int row = lr + rr;
            float4 av = *reinterpret_cast<const float4*>(
                X + (size_t)(m0 + row) * FINv + k0 + lc4);
            uint4 at = make_uint4(cvt_tf32(av.x), cvt_tf32(av.y),
                                  cvt_tf32(av.z), cvt_tf32(av.w));
            *reinterpret_cast<uint4*>(&As[row * P1ROW + lc4]) = at;
            float4 bv = *reinterpret_cast<const float4*>(
                W + (size_t)(n0 + row) * FINv + k0 + lc4);
            uint4 bt = make_uint4(cvt_tf32(bv.x), cvt_tf32(bv.y),
                                  cvt_tf32(bv.z), cvt_tf32(bv.w));
            *reinterpret_cast<uint4*>(&Bs[row * P1ROW + lc4]) = bt;
        }
        __syncthreads();

#pragma unroll
        for (int kk = 0; kk < 32; kk += 8) {
            unsigned afr[4][4], bfr[4][2];
#pragma unroll
            for (int mi = 0; mi < 4; mi++) {
                int base = (wm + mi * 16 + g) * P1ROW + kk + t;
                afr[mi][0] = As[base];
                afr[mi][1] = As[base + 8 * P1ROW];
                afr[mi][2] = As[base + 4];
                afr[mi][3] = As[base + 8 * P1ROW + 4];
            }
#pragma unroll
            for (int nj = 0; nj < 4; nj++) {
                int bb = (wn + nj * 8 + g) * P1ROW + kk + t;
                bfr[nj][0] = Bs[bb];
                bfr[nj][1] = Bs[bb + 4];
            }
#pragma unroll
            for (int mi = 0; mi < 4; mi++)
#pragma unroll
                for (int nj = 0; nj < 4; nj++)
                    mma_tf32(acc[mi][nj], afr[mi], bfr[nj]);
        }
        __syncthreads();
    }

#pragma unroll
    for (int nj = 0; nj < 4; nj++) {
        int n = n0 + wn + nj * 8 + 2 * t;
        float bs0 = bih[n] + bhh[n];
        float bs1 = bih[n + 1] + bhh[n + 1];
#pragma unroll
        for (int mi = 0; mi < 4; mi++) {
            int row = m0 + wm + mi * 16 + g;
            float2 v0 = make_float2(acc[mi][nj][0] + bs0, acc[mi][nj][1] + bs1);
            float2 v1 = make_float2(acc[mi][nj][2] + bs0, acc[mi][nj][3] + bs1);
            *reinterpret_cast<float2*>(&g_gx[(size_t)row * G4 + n])       = v0;
            *reinterpret_cast<float2*>(&g_gx[(size_t)(row + 8) * G4 + n]) = v1;
        }
    }
}

// ===========================================================================
// Phase 2: persistent recurrence, tensor-core mainloop, 256 threads (8 warps,
// 2 per SMSP for latency hiding).
// Block bx owns hidden units [4bx,4bx+4) = 16 gate-cols. Warp = (colgrp, batgrp):
// colgrp = wid>>2 selects cols [8*colgrp, +8), batgrp = wid&3 selects batches
// [16*batgrp, +16). Exact-fp32 recurrence via 2-term tf32 split:
// acc = gx + W1*h1 + W1*h2 + W2*h1. c(t-1) in registers (1 item/thread).
// ===========================================================================
#define HPAD 516
#define WPAD 516
#define W1_OFF 0
#define W2_OFF (16 * WPAD)
#define H_OFF  (32 * WPAD)
#define EX_OFF (H_OFF + 64 * HPAD)
#define SM2_FLOATS (EX_OFF + 16 * 68)   // 50624 floats = 202496 B

__global__ __launch_bounds__(256, 1) void lstm_rec_kernel(
    const float* __restrict__ whh,   // [2048][512]
    float* __restrict__ out)
{
    extern __shared__ float sm[];
    unsigned* w1_s = reinterpret_cast<unsigned*>(sm + W1_OFF);  // [16][WPAD]
    unsigned* w2_s = reinterpret_cast<unsigned*>(sm + W2_OFF);  // [16][WPAD]
    float*    h_s  = sm + H_OFF;                                 // [64][HPAD]
    float*    ex   = sm + EX_OFF;                                // [16][68]

    float* hs_out = out;
    float* cs_out = out + (size_t)Sv * Bv * Hv;

    const int tid    = threadIdx.x;
    const int wid    = tid >> 5;
    const int lane   = tid & 31;
    const int g      = lane >> 2;
    const int t      = lane & 3;
    const int u0     = blockIdx.x * 4;
    const int colgrp = wid >> 2;         // 0..1 -> cols [8*colgrp, +8)
    const int bb     = (wid & 3) * 16;   // batch base

    // W_hh split into (W1, W2) tf32 pair, once.
    for (int i = tid; i < 16 * Hv; i += 256) {
        int c = i >> 9, k = i & (Hv - 1);
        int gr = ((c >> 2) * Hv) + u0 + (c & 3);
        float w = whh[(size_t)gr * Hv + k];
        unsigned w1 = cvt_tf32(w);
        w1_s[c * WPAD + k] = w1;
        w2_s[c * WPAD + k] = cvt_tf32(w - __uint_as_float(w1));
    }

    unsigned bar_base = 0;
    if (tid == 0) bar_base = atomicAdd(&g_gen, 0u);

    // This thread's acc covers rows {bb+g, bb+g+8} x cols {c, c+1},
    // where c = colgrp*8 + 2t. Gate col: gate=c>>2, unit=c&3 (c even -> c+1
    // is the same gate, adjacent unit).
    const int c_lo  = colgrp * 8 + 2 * t;
    const int gcol  = ((c_lo >> 2) * Hv) + u0 + (c_lo & 3);

    // W fragment base offsets (col = colgrp*8 + g)
    const int wrow = (colgrp * 8 + g) * WPAD + t;
    // h fragment row offsets
    const int r0 = (bb + g) * HPAD + t;
    const int r1 = (bb + g + 8) * HPAD + t;

    // Elementwise mapping: ONE (unit,batch) item per thread; c in register.
    const int u_e = tid & 3;
    const int b_e = tid >> 2;     // 0..63
    float cpv = 0.f;

    __syncthreads();

    for (int t_s = 0; t_s < Sv; t_s++) {
        // ---- stage h(t-1) into smem (fp32) ----
        if (t_s == 0) {
            for (int i = tid; i < 64 * HPAD; i += 256) h_s[i] = 0.f;
        } else {
            const float* hp = hs_out + (size_t)(t_s - 1) * Bv * Hv;
#pragma unroll 8
            for (int i = 0; i < 32; i++) {
                int f = tid + 256 * i;             // f4 index < 8192
                float4 v = __ldcg(reinterpret_cast<const float4*>(hp) + f);
                int row = f >> 7, col4 = f & 127;
                *reinterpret_cast<float4*>(h_s + row * HPAD + col4 * 4) = v;
            }
        }

        // ---- init accumulators from gx (bias folded in phase 1) ----
        float acc[4];
        {
            const float* gxt = g_gx + (size_t)t_s * (Bv * G4);
            float2 lo = *reinterpret_cast<const float2*>(
                gxt + (size_t)(bb + g) * G4 + gcol);
            float2 hi = *reinterpret_cast<const float2*>(
                gxt + (size_t)(bb + g + 8) * G4 + gcol);
            acc[0] = lo.x; acc[1] = lo.y; acc[2] = hi.x; acc[3] = hi.y;
        }
        __syncthreads();

        // ---- tensor-core recurrent GEMM, exact-fp32 via 2-term split ----
#pragma unroll 8
        for (int kt = 0; kt < 64; kt++) {
            int k0 = kt * 8;
            float h0 = h_s[r0 + k0];
            float h1 = h_s[r1 + k0];
            float h2 = h_s[r0 + k0 + 4];
            float h3 = h_s[r1 + k0 + 4];
            unsigned a1[4], a2[4];
            a1[0] = cvt_tf32(h0); a2[0] = cvt_tf32(h0 - __uint_as_float(a1[0]));
            a1[1] = cvt_tf32(h1); a2[1] = cvt_tf32(h1 - __uint_as_float(a1[1]));
            a1[2] = cvt_tf32(h2); a2[2] = cvt_tf32(h2 - __uint_as_float(a1[2]));
            a1[3] = cvt_tf32(h3); a2[3] = cvt_tf32(h3 - __uint_as_float(a1[3]));
            unsigned b1[2], b2[2];
            b1[0] = w1_s[wrow + k0]; b1[1] = w1_s[wrow + k0 + 4];
            b2[0] = w2_s[wrow + k0]; b2[1] = w2_s[wrow + k0 + 4];
            mma_tf32(acc, a1, b1);   // W1*h1
            mma_tf32(acc, a2, b1);   // W1*h2
            mma_tf32(acc, a1, b2);   // W2*h1
        }

        // ---- exchange gate pre-activations ----
        ex[c_lo * 68 + bb + g]           = acc[0];
        ex[(c_lo + 1) * 68 + bb + g]     = acc[1];
        ex[c_lo * 68 + bb + g + 8]       = acc[2];
        ex[(c_lo + 1) * 68 + bb + g + 8] = acc[3];
        __syncthreads();

        // ---- LSTM update: one (unit,batch) per thread, c in register ----
        {
            float gi = ex[(0  + u_e) * 68 + b_e];
            float gf = ex[(4  + u_e) * 68 + b_e];
            float gg = ex[(8  + u_e) * 68 + b_e];
            float go = ex[(12 + u_e) * 68 + b_e];
            float si = 1.f / (1.f + expf(-gi));
            float sf = 1.f / (1.f + expf(-gf));
            float so = 1.f / (1.f + expf(-go));
            float tg = tanhf(gg);
            float cc = sf * cpv + si * tg;
            cpv = cc;
            float hh = so * tanhf(cc);
            size_t o = (size_t)t_s * Bv * Hv + (size_t)b_e * Hv + u0 + u_e;
            __stcg(hs_out + o, hh);
            __stcg(cs_out + o, cc);
        }

        // ---- grid barrier between steps ----
        if (t_s < Sv - 1) {
            __threadfence();
            __syncthreads();
            if (tid == 0) {
                unsigned target = bar_base + (unsigned)t_s + 1u;
                if (atomicAdd(&g_count, 1u) == NBLK - 1u) {
                    atomicExch(&g_count, 0u);
                    __threadfence();
                    atomicExch(&g_gen, target);
                } else {
                    while ((int)(atomicAdd(&g_gen, 0u) - target) < 0) { }
                }
                __threadfence();
            }
            __syncthreads();
        }
    }
}

// ===========================================================================
// Launch
// ===========================================================================
extern "C" void kernel_launch(void* const* d_in, const int* in_sizes, int n_in,
                              void* d_out, int out_size)
{
    const float* seq  = (const float*)d_in[0];
    const float* w_ih = (const float*)d_in[1];
    const float* w_hh = (const float*)d_in[2];
    const float* b_ih = (const float*)d_in[3];
    const float* b_hh = (const float*)d_in[4];
    float* out = (float*)d_out;

    const int smem_p2 = SM2_FLOATS * (int)sizeof(float);   // 202496 B
    cudaFuncSetAttribute(lstm_rec_kernel,
                         cudaFuncAttributeMaxDynamicSharedMemorySize, smem_p2);

    dim3 g1(G4 / 128, (Sv * Bv) / 128);   // (16, 256)
    gemm_x_tf32<<<g1, 256>>>(seq, w_ih, b_ih, b_hh);
    lstm_rec_kernel<<<NBLK, 256, smem_p2>>>(w_hh, out);
}

// round 12
// speedup vs baseline: 2.0576x; 1.4034x over previous
#include <cuda_runtime.h>
#include <math.h>

// Problem constants
#define Sv   512
#define Bv   64
#define FINv 512
#define Hv   512
#define G4   2048   // 4*H

__device__ float g_gx[(size_t)Sv * Bv * G4];

// Grid-barrier state (generation-based; leftovers across replays harmless).
__device__ unsigned int g_count = 0;
__device__ unsigned int g_gen   = 0;

#define NBLK 128

__device__ __forceinline__ unsigned cvt_tf32(float x) {
    unsigned u;
    asm("cvt.rna.tf32.f32 %0, %1;" : "=r"(u) : "f"(x));
    return u;
}

__device__ __forceinline__ void mma_tf32(float c[4], const unsigned a[4],
                                         const unsigned b[2]) {
    asm("mma.sync.aligned.m16n8k8.row.col.f32.tf32.tf32.f32 "
        "{%0,%1,%2,%3}, {%4,%5,%6,%7}, {%8,%9}, {%0,%1,%2,%3};"
        : "+f"(c[0]), "+f"(c[1]), "+f"(c[2]), "+f"(c[3])
        : "r"(a[0]), "r"(a[1]), "r"(a[2]), "r"(a[3]),
          "r"(b[0]), "r"(b[1]));
}

__device__ __forceinline__ void mma_bf16(float c[4], const unsigned a[4],
                                         const unsigned b[2]) {
    asm("mma.sync.aligned.m16n8k16.row.col.f32.bf16.bf16.f32 "
        "{%0,%1,%2,%3}, {%4,%5,%6,%7}, {%8,%9}, {%0,%1,%2,%3};"
        : "+f"(c[0]), "+f"(c[1]), "+f"(c[2]), "+f"(c[3])
        : "r"(a[0]), "r"(a[1]), "r"(a[2]), "r"(a[3]),
          "r"(b[0]), "r"(b[1]));
}

// Split (e0, e1) into packed bf16x2 (hi word) + packed bf16x2 residual (lo).
// Word layout: element with even k in the LOW 16 bits (mma operand order).
__device__ __forceinline__ void bf16_split2(float e0, float e1,
                                            unsigned& hi, unsigned& lo) {
    asm("cvt.rn.bf16x2.f32 %0, %1, %2;" : "=r"(hi) : "f"(e1), "f"(e0));
    float f0 = __uint_as_float(hi << 16);
    float f1 = __uint_as_float(hi & 0xffff0000u);
    float r0 = e0 - f0;
    float r1 = e1 - f1;
    asm("cvt.rn.bf16x2.f32 %0, %1, %2;" : "=r"(lo) : "f"(r1), "f"(r0));
}

// ===========================================================================
// Phase 1: gx = X[32768,512] @ W_ih^T[512,2048] + (b_ih + b_hh)
// tf32 mma.m16n8k8, 128x128 block tile, 8 warps, 64x32 warp tile. (R6, kept.)
// ===========================================================================
#define P1ROW 36

__global__ __launch_bounds__(256, 2) void gemm_x_tf32(
    const float* __restrict__ X,
    const float* __restrict__ W,
    const float* __restrict__ bih,
    const float* __restrict__ bhh)
{
    __shared__ unsigned As[128 * P1ROW];
    __shared__ unsigned Bs[128 * P1ROW];

    const int tid  = threadIdx.x;
    const int wid  = tid >> 5;
    const int lane = tid & 31;
    const int g    = lane >> 2;
    const int t    = lane & 3;

    const int m0 = blockIdx.y * 128;
    const int n0 = blockIdx.x * 128;
    const int wm = (wid >> 2) * 64;
    const int wn = (wid & 3) * 32;

    const int lr  = tid >> 3;
    const int lc4 = (tid & 7) * 4;

    float acc[4][4][4];
#pragma unroll
    for (int mi = 0; mi < 4; mi++)
#pragma unroll
        for (int nj = 0; nj < 4; nj++)
#pragma unroll
            for (int q = 0; q < 4; q++) acc[mi][nj][q] = 0.f;

    for (int k0 = 0; k0 < FINv; k0 += 32) {
#pragma unroll
        for (int rr = 0; rr < 128; rr += 32) {
            int row = lr + rr;
            float4 av = *reinterpret_cast<const float4*>(
                X + (size_t)(m0 + row) * FINv + k0 + lc4);
            uint4 at = make_uint4(cvt_tf32(av.x), cvt_tf32(av.y),
                                  cvt_tf32(av.z), cvt_tf32(av.w));
            *reinterpret_cast<uint4*>(&As[row * P1ROW + lc4]) = at;
            float4 bv = *reinterpret_cast<const float4*>(
                W + (size_t)(n0 + row) * FINv + k0 + lc4);
            uint4 bt = make_uint4(cvt_tf32(bv.x), cvt_tf32(bv.y),
                                  cvt_tf32(bv.z), cvt_tf32(bv.w));
            *reinterpret_cast<uint4*>(&Bs[row * P1ROW + lc4]) = bt;
        }
        __syncthreads();

#pragma unroll
        for (int kk = 0; kk < 32; kk += 8) {
            unsigned afr[4][4], bfr[4][2];
#pragma unroll
            for (int mi = 0; mi < 4; mi++) {
                int base = (wm + mi * 16 + g) * P1ROW + kk + t;
                afr[mi][0] = As[base];
                afr[mi][1] = As[base + 8 * P1ROW];
                afr[mi][2] = As[base + 4];
                afr[mi][3] = As[base + 8 * P1ROW + 4];
            }
#pragma unroll
            for (int nj = 0; nj < 4; nj++) {
                int bb = (wn + nj * 8 + g) * P1ROW + kk + t;
                bfr[nj][0] = Bs[bb];
                bfr[nj][1] = Bs[bb + 4];
            }
#pragma unroll
            for (int mi = 0; mi < 4; mi++)
#pragma unroll
                for (int nj = 0; nj < 4; nj++)
                    mma_tf32(acc[mi][nj], afr[mi], bfr[nj]);
        }
        __syncthreads();
    }

#pragma unroll
    for (int nj = 0; nj < 4; nj++) {
        int n = n0 + wn + nj * 8 + 2 * t;
        float bs0 = bih[n] + bhh[n];
        float bs1 = bih[n + 1] + bhh[n + 1];
#pragma unroll
        for (int mi = 0; mi < 4; mi++) {
            int row = m0 + wm + mi * 16 + g;
            float2 v0 = make_float2(acc[mi][nj][0] + bs0, acc[mi][nj][1] + bs1);
            float2 v1 = make_float2(acc[mi][nj][2] + bs0, acc[mi][nj][3] + bs1);
            *reinterpret_cast<float2*>(&g_gx[(size_t)row * G4 + n])       = v0;
            *reinterpret_cast<float2*>(&g_gx[(size_t)(row + 8) * G4 + n]) = v1;
        }
    }
}

// ===========================================================================
// Phase 2: persistent recurrence, bf16-pair tensor-core mainloop.
// 128 blocks x 256 threads (8 warps). Block bx owns hidden units [4bx,4bx+4)
// = 16 gate-cols. Warp = (kh = wid>>2: K half) x (bb = (wid&3)*16: batches).
// Warp tile m16 x n16 x k256 via m16n8k16 bf16 mmas on PRE-SPLIT operands:
//   acc = gx + Whi*Hhi + Whi*Hlo + Wlo*Hhi    (fp32 accumulate)
// Operands stored as packed bf16x2-of-consecutive-k words; mainloop is pure
// LDS.32 -> mma. Split-K=2 reduced through a 2-slab ex buffer in the fused
// epilogue. c(t-1) in registers; generation barrier between steps.
// ===========================================================================
#define HS 260     // words per row (256 + 4 pad); 260 % 32 = 4 -> banks 4g+t
#define WHI_OFF 0
#define WLO_OFF (16 * HS)                    // 4160
#define HHI_OFF (32 * HS)                    // 8320
#define HLO_OFF (HHI_OFF + 64 * HS)          // 24960
#define EX_OFF  (HLO_OFF + 64 * HS)          // 41600
#define EXSLAB  (16 * 68)
#define SM2_WORDS (EX_OFF + 2 * EXSLAB)      // 43776 words = 175104 B

__global__ __launch_bounds__(256, 1) void lstm_rec_kernel(
    const float* __restrict__ whh,   // [2048][512]
    float* __restrict__ out)
{
    extern __shared__ unsigned smu[];
    unsigned* w_hi = smu + WHI_OFF;
    unsigned* w_lo = smu + WLO_OFF;
    unsigned* h_hi = smu + HHI_OFF;
    unsigned* h_lo = smu + HLO_OFF;
    float*    ex   = reinterpret_cast<float*>(smu + EX_OFF);  // [2][16][68]

    float* hs_out = out;
    float* cs_out = out + (size_t)Sv * Bv * Hv;

    const int tid  = threadIdx.x;
    const int wid  = tid >> 5;
    const int lane = tid & 31;
    const int g    = lane >> 2;
    const int t    = lane & 3;
    const int u0   = blockIdx.x * 4;
    const int kh   = wid >> 2;           // K half: k in [kh*256, +256)
    const int bb   = (wid & 3) * 16;     // batch base

    // W_hh split into packed bf16 (hi, lo) pair words, once.
    // Word j of col c packs k = 2j, 2j+1.
    for (int i = tid; i < 16 * 256; i += 256) {
        int c = i >> 8, j = i & 255;
        int gr = ((c >> 2) * Hv) + u0 + (c & 3);
        float2 wv = *reinterpret_cast<const float2*>(whh + (size_t)gr * Hv + 2 * j);
        unsigned hi, lo;
        bf16_split2(wv.x, wv.y, hi, lo);
        w_hi[c * HS + j] = hi;
        w_lo[c * HS + j] = lo;
    }

    unsigned bar_base = 0;
    if (tid == 0) bar_base = atomicAdd(&g_gen, 0u);

    // Fragment base offsets (word indices)
    const int a0 = (bb + g) * HS + t;        // A rows g / g+8
    const int a1 = (bb + g + 8) * HS + t;
    const int b0 = g * HS + t;               // B cols 0-7  (n8 tile 0)
    const int b1 = (8 + g) * HS + t;         // B cols 8-15 (n8 tile 1)
    const int jh = kh * 128;                 // K-half word base

    // Accumulator cols: nt*8 + 2t, +1 (same gate for both since 2t even)
    int gcol[2];
#pragma unroll
    for (int nt = 0; nt < 2; nt++) {
        int c = nt * 8 + 2 * t;
        gcol[nt] = ((c >> 2) * Hv) + u0 + (c & 3);
    }

    // Elementwise mapping: one (unit,batch) per thread; c in register.
    const int u_e = tid & 3;
    const int b_e = tid >> 2;
    float cpv = 0.f;

    __syncthreads();

    for (int t_s = 0; t_s < Sv; t_s++) {
        // ---- stage h(t-1): fp32 global -> packed bf16 (hi,lo) smem ----
        if (t_s == 0) {
            for (int i = tid; i < 64 * HS; i += 256) {
                h_hi[i] = 0u; h_lo[i] = 0u;
            }
        } else {
            const float* hp = hs_out + (size_t)(t_s - 1) * Bv * Hv;
#pragma unroll 8
            for (int i = 0; i < 32; i++) {
                int f = tid + 256 * i;             // float4 index < 8192
                float4 v = __ldcg(reinterpret_cast<const float4*>(hp) + f);
                int row = f >> 7, j = (f & 127) * 2;
                unsigned hi0, lo0, hi1, lo1;
                bf16_split2(v.x, v.y, hi0, lo0);
                bf16_split2(v.z, v.w, hi1, lo1);
                int base = row * HS + j;
                h_hi[base]     = hi0;  h_hi[base + 1] = hi1;
                h_lo[base]     = lo0;  h_lo[base + 1] = lo1;
            }
        }

        // ---- init accumulators: kh=0 warps carry gx, kh=1 zeros ----
        float acc[2][4];
        if (kh == 0) {
            const float* gxt = g_gx + (size_t)t_s * (Bv * G4);
#pragma unroll
            for (int nt = 0; nt < 2; nt++) {
                float2 lo = *reinterpret_cast<const float2*>(
                    gxt + (size_t)(bb + g) * G4 + gcol[nt]);
                float2 hi = *reinterpret_cast<const float2*>(
                    gxt + (size_t)(bb + g + 8) * G4 + gcol[nt]);
                acc[nt][0] = lo.x; acc[nt][1] = lo.y;
                acc[nt][2] = hi.x; acc[nt][3] = hi.y;
            }
        } else {
#pragma unroll
            for (int nt = 0; nt < 2; nt++)
#pragma unroll
                for (int q = 0; q < 4; q++) acc[nt][q] = 0.f;
        }
        __syncthreads();

        // ---- bf16-pair recurrent GEMM: 16 x k16 tiles, pure LDS->mma ----
#pragma unroll 4
        for (int kt = 0; kt < 16; kt++) {
            int jb = jh + kt * 8;
            unsigned ah[4], al[4], bh[2][2], bl[2][2];
            ah[0] = h_hi[a0 + jb];     ah[1] = h_hi[a1 + jb];
            ah[2] = h_hi[a0 + jb + 4]; ah[3] = h_hi[a1 + jb + 4];
            al[0] = h_lo[a0 + jb];     al[1] = h_lo[a1 + jb];
            al[2] = h_lo[a0 + jb + 4]; al[3] = h_lo[a1 + jb + 4];
            bh[0][0] = w_hi[b0 + jb];  bh[0][1] = w_hi[b0 + jb + 4];
            bh[1][0] = w_hi[b1 + jb];  bh[1][1] = w_hi[b1 + jb + 4];
            bl[0][0] = w_lo[b0 + jb];  bl[0][1] = w_lo[b0 + jb + 4];
            bl[1][0] = w_lo[b1 + jb];  bl[1][1] = w_lo[b1 + jb + 4];
#pragma unroll
            for (int nt = 0; nt < 2; nt++) {
                mma_bf16(acc[nt], ah, bh[nt]);   // Whi*Hhi
                mma_bf16(acc[nt], al, bh[nt]);   // Whi*Hlo
                mma_bf16(acc[nt], ah, bl[nt]);   // Wlo*Hhi
            }
        }

        // ---- write split-K partials to ex[kh] ----
#pragma unroll
        for (int nt = 0; nt < 2; nt++) {
            int c = nt * 8 + 2 * t;
            float* exs = ex + kh * EXSLAB;
            exs[c * 68 + bb + g]           = acc[nt][0];
            exs[(c + 1) * 68 + bb + g]     = acc[nt][1];
            exs[c * 68 + bb + g + 8]       = acc[nt][2];
            exs[(c + 1) * 68 + bb + g + 8] = acc[nt][3];
        }
        __syncthreads();

        // ---- fused reduce + LSTM update: one (unit,batch)/thread ----
        {
            float gi = ex[(0  + u_e) * 68 + b_e] + ex[EXSLAB + (0  + u_e) * 68 + b_e];
            float gf = ex[(4  + u_e) * 68 + b_e] + ex[EXSLAB + (4  + u_e) * 68 + b_e];
            float gg = ex[(8  + u_e) * 68 + b_e] + ex[EXSLAB + (8  + u_e) * 68 + b_e];
            float go = ex[(12 + u_e) * 68 + b_e] + ex[EXSLAB + (12 + u_e) * 68 + b_e];
            float si = 1.f / (1.f + expf(-gi));
            float sf = 1.f / (1.f + expf(-gf));
            float so = 1.f / (1.f + expf(-go));
            float tg = tanhf(gg);
            float cc = sf * cpv + si * tg;
            cpv = cc;
            float hh = so * tanhf(cc);
            size_t o = (size_t)t_s * Bv * Hv + (size_t)b_e * Hv + u0 + u_e;
            __stcg(hs_out + o, hh);
            __stcg(cs_out + o, cc);
        }

        // ---- grid barrier between steps ----
        if (t_s < Sv - 1) {
            __threadfence();
            __syncthreads();
            if (tid == 0) {
                unsigned target = bar_base + (unsigned)t_s + 1u;
                if (atomicAdd(&g_count, 1u) == NBLK - 1u) {
                    atomicExch(&g_count, 0u);
                    __threadfence();
                    atomicExch(&g_gen, target);
                } else {
                    while ((int)(atomicAdd(&g_gen, 0u) - target) < 0) { }
                }
                __threadfence();
            }
            __syncthreads();
        }
    }
}

// ===========================================================================
// Launch
// ===========================================================================
extern "C" void kernel_launch(void* const* d_in, const int* in_sizes, int n_in,
                              void* d_out, int out_size)
{
    const float* seq  = (const float*)d_in[0];
    const float* w_ih = (const float*)d_in[1];
    const float* w_hh = (const float*)d_in[2];
    const float* b_ih = (const float*)d_in[3];
    const float* b_hh = (const float*)d_in[4];
    float* out = (float*)d_out;

    const int smem_p2 = SM2_WORDS * (int)sizeof(unsigned);   // 175104 B
    cudaFuncSetAttribute(lstm_rec_kernel,
                         cudaFuncAttributeMaxDynamicSharedMemorySize, smem_p2);

    dim3 g1(G4 / 128, (Sv * Bv) / 128);   // (16, 256)
    gemm_x_tf32<<<g1, 256>>>(seq, w_ih, b_ih, b_hh);
    lstm_rec_kernel<<<NBLK, 256, smem_p2>>>(w_hh, out);
}

// round 13
// speedup vs baseline: 2.1156x; 1.0282x over previous
#include <cuda_runtime.h>
#include <math.h>

// Problem constants
#define Sv   512
#define Bv   64
#define FINv 512
#define Hv   512
#define G4   2048   // 4*H

__device__ float g_gx[(size_t)Sv * Bv * G4];

// h(t-1) in pre-split packed-bf16 form, written by producers each step.
__device__ __align__(16) unsigned short g_hhi[Bv * Hv];
__device__ __align__(16) unsigned short g_hlo[Bv * Hv];

// Grid-barrier state (generation-based; leftovers across replays harmless).
__device__ unsigned int g_count = 0;
__device__ unsigned int g_gen   = 0;

#define NBLK 128

__device__ __forceinline__ unsigned cvt_tf32(float x) {
    unsigned u;
    asm("cvt.rna.tf32.f32 %0, %1;" : "=r"(u) : "f"(x));
    return u;
}

__device__ __forceinline__ void mma_tf32(float c[4], const unsigned a[4],
                                         const unsigned b[2]) {
    asm("mma.sync.aligned.m16n8k8.row.col.f32.tf32.tf32.f32 "
        "{%0,%1,%2,%3}, {%4,%5,%6,%7}, {%8,%9}, {%0,%1,%2,%3};"
        : "+f"(c[0]), "+f"(c[1]), "+f"(c[2]), "+f"(c[3])
        : "r"(a[0]), "r"(a[1]), "r"(a[2]), "r"(a[3]),
          "r"(b[0]), "r"(b[1]));
}

__device__ __forceinline__ void mma_bf16(float c[4], const unsigned a[4],
                                         const unsigned b[2]) {
    asm("mma.sync.aligned.m16n8k16.row.col.f32.bf16.bf16.f32 "
        "{%0,%1,%2,%3}, {%4,%5,%6,%7}, {%8,%9}, {%0,%1,%2,%3};"
        : "+f"(c[0]), "+f"(c[1]), "+f"(c[2]), "+f"(c[3])
        : "r"(a[0]), "r"(a[1]), "r"(a[2]), "r"(a[3]),
          "r"(b[0]), "r"(b[1]));
}

// Split (e0, e1) into packed bf16x2 (hi) + packed bf16x2 residual (lo).
// Even-k element in the LOW 16 bits (mma operand order).
__device__ __forceinline__ void bf16_split2(float e0, float e1,
                                            unsigned& hi, unsigned& lo) {
    asm("cvt.rn.bf16x2.f32 %0, %1, %2;" : "=r"(hi) : "f"(e1), "f"(e0));
    float f0 = __uint_as_float(hi << 16);
    float f1 = __uint_as_float(hi & 0xffff0000u);
    float r0 = e0 - f0;
    float r1 = e1 - f1;
    asm("cvt.rn.bf16x2.f32 %0, %1, %2;" : "=r"(lo) : "f"(r1), "f"(r0));
}

__device__ __forceinline__ unsigned short bf16_of(float x) {
    unsigned short h;
    asm("cvt.rn.bf16.f32 %0, %1;" : "=h"(h) : "f"(x));
    return h;
}

// ===========================================================================
// Phase 1: gx = X[32768,512] @ W_ih^T[512,2048] + (b_ih + b_hh)
// tf32 mma.m16n8k8, 128x128 block tile, 8 warps, 64x32 warp tile. (R6, kept.)
// ===========================================================================
#define P1ROW 36

__global__ __launch_bounds__(256, 2) void gemm_x_tf32(
    const float* __restrict__ X,
    const float* __restrict__ W,
    const float* __restrict__ bih,
    const float* __restrict__ bhh)
{
    __shared__ unsigned As[128 * P1ROW];
    __shared__ unsigned Bs[128 * P1ROW];

    const int tid  = threadIdx.x;
    const int wid  = tid >> 5;
    const int lane = tid & 31;
    const int g    = lane >> 2;
    const int t    = lane & 3;

    const int m0 = blockIdx.y * 128;
    const int n0 = blockIdx.x * 128;
    const int wm = (wid >> 2) * 64;
    const int wn = (wid & 3) * 32;

    const int lr  = tid >> 3;
    const int lc4 = (tid & 7) * 4;

    float acc[4][4][4];
#pragma unroll
    for (int mi = 0; mi < 4; mi++)
#pragma unroll
        for (int nj = 0; nj < 4; nj++)
#pragma unroll
            for (int q = 0; q < 4; q++) acc[mi][nj][q] = 0.f;

    for (int k0 = 0; k0 < FINv; k0 += 32) {
#pragma unroll
        for (int rr = 0; rr < 128; rr += 32) {
            int row = lr + rr;
            float4 av = *reinterpret_cast<const float4*>(
                X + (size_t)(m0 + row) * FINv + k0 + lc4);
            uint4 at = make_uint4(cvt_tf32(av.x), cvt_tf32(av.y),
                                  cvt_tf32(av.z), cvt_tf32(av.w));
            *reinterpret_cast<uint4*>(&As[row * P1ROW + lc4]) = at;
            float4 bv = *reinterpret_cast<const float4*>(
                W + (size_t)(n0 + row) * FINv + k0 + lc4);
            uint4 bt = make_uint4(cvt_tf32(bv.x), cvt_tf32(bv.y),
                                  cvt_tf32(bv.z), cvt_tf32(bv.w));
            *reinterpret_cast<uint4*>(&Bs[row * P1ROW + lc4]) = bt;
        }
        __syncthreads();

#pragma unroll
        for (int kk = 0; kk < 32; kk += 8) {
            unsigned afr[4][4], bfr[4][2];
#pragma unroll
            for (int mi = 0; mi < 4; mi++) {
                int base = (wm + mi * 16 + g) * P1ROW + kk + t;
                afr[mi][0] = As[base];
                afr[mi][1] = As[base + 8 * P1ROW];
                afr[mi][2] = As[base + 4];
                afr[mi][3] = As[base + 8 * P1ROW + 4];
            }
#pragma unroll
            for (int nj = 0; nj < 4; nj++) {
                int bb = (wn + nj * 8 + g) * P1ROW + kk + t;
                bfr[nj][0] = Bs[bb];
                bfr[nj][1] = Bs[bb + 4];
            }
#pragma unroll
            for (int mi = 0; mi < 4; mi++)
#pragma unroll
                for (int nj = 0; nj < 4; nj++)
                    mma_tf32(acc[mi][nj], afr[mi], bfr[nj]);
        }
        __syncthreads();
    }

#pragma unroll
    for (int nj = 0; nj < 4; nj++) {
        int n = n0 + wn + nj * 8 + 2 * t;
        float bs0 = bih[n] + bhh[n];
        float bs1 = bih[n + 1] + bhh[n + 1];
#pragma unroll
        for (int mi = 0; mi < 4; mi++) {
            int row = m0 + wm + mi * 16 + g;
            float2 v0 = make_float2(acc[mi][nj][0] + bs0, acc[mi][nj][1] + bs1);
            float2 v1 = make_float2(acc[mi][nj][2] + bs0, acc[mi][nj][3] + bs1);
            *reinterpret_cast<float2*>(&g_gx[(size_t)row * G4 + n])       = v0;
            *reinterpret_cast<float2*>(&g_gx[(size_t)(row + 8) * G4 + n]) = v1;
        }
    }
}

// ===========================================================================
// Phase 2: persistent recurrence, bf16-pair tensor cores, 512 threads
// (16 warps, 4/SMSP). Block bx owns hidden units [4bx,4bx+4) = 16 gate-cols.
// Warp = (kq = wid>>2: K quarter) x (bb = (wid&3)*16: batches).
//   acc = gx + Whi*Hhi + Whi*Hlo + Wlo*Hhi   (fp32 accumulate)
// h arrives PRE-SPLIT from producers (g_hhi/g_hlo): staging is a pure copy.
// Split-K=4 reduced through a 4-slab ex buffer in the fused epilogue
// (threads tid<256, one (unit,batch) each, c in registers).
// ===========================================================================
#define HS 260     // words per row (256 + 4 pad)
#define WHI_OFF 0
#define WLO_OFF (16 * HS)                    // 4160
#define HHI_OFF (32 * HS)                    // 8320
#define HLO_OFF (HHI_OFF + 64 * HS)          // 24960
#define EX_OFF  (HLO_OFF + 64 * HS)          // 41600
#define EXSLAB  (16 * 68)
#define SM2_WORDS (EX_OFF + 4 * EXSLAB)      // 45952 words = 183808 B

__global__ __launch_bounds__(512, 1) void lstm_rec_kernel(
    const float* __restrict__ whh,   // [2048][512]
    float* __restrict__ out)
{
    extern __shared__ unsigned smu[];
    unsigned* w_hi = smu + WHI_OFF;
    unsigned* w_lo = smu + WLO_OFF;
    unsigned* h_hi = smu + HHI_OFF;
    unsigned* h_lo = smu + HLO_OFF;
    float*    ex   = reinterpret_cast<float*>(smu + EX_OFF);  // [4][16][68]

    float* hs_out = out;
    float* cs_out = out + (size_t)Sv * Bv * Hv;

    const int tid  = threadIdx.x;
    const int wid  = tid >> 5;
    const int lane = tid & 31;
    const int g    = lane >> 2;
    const int t    = lane & 3;
    const int u0   = blockIdx.x * 4;
    const int kq   = wid >> 2;           // K quarter: words [kq*64, +64)
    const int bb   = (wid & 3) * 16;     // batch base

    // W_hh split into packed bf16 (hi, lo) pair words, once.
    for (int i = tid; i < 16 * 256; i += 512) {
        int c = i >> 8, j = i & 255;
        int gr = ((c >> 2) * Hv) + u0 + (c & 3);
        float2 wv = *reinterpret_cast<const float2*>(whh + (size_t)gr * Hv + 2 * j);
        unsigned hi, lo;
        bf16_split2(wv.x, wv.y, hi, lo);
        w_hi[c * HS + j] = hi;
        w_lo[c * HS + j] = lo;
    }

    unsigned bar_base = 0;
    if (tid == 0) bar_base = atomicAdd(&g_gen, 0u);

    // Fragment base offsets (word indices)
    const int a0 = (bb + g) * HS + t;
    const int a1 = (bb + g + 8) * HS + t;
    const int b0 = g * HS + t;
    const int b1 = (8 + g) * HS + t;
    const int jh = kq * 64;

    // Accumulator cols: nt*8 + 2t, +1 (adjacent units of the same gate)
    int gcol[2];
#pragma unroll
    for (int nt = 0; nt < 2; nt++) {
        int c = nt * 8 + 2 * t;
        gcol[nt] = ((c >> 2) * Hv) + u0 + (c & 3);
    }

    // Elementwise mapping (threads tid<256): one (unit,batch); c in register.
    const int u_e = tid & 3;
    const int b_e = (tid >> 2) & 63;
    float cpv = 0.f;

    __syncthreads();

    for (int t_s = 0; t_s < Sv; t_s++) {
        // ---- prefetch gx into regs (overlaps the barrier wait) ----
        float gxv[2][4];
        if (kq == 0) {
            const float* gxt = g_gx + (size_t)t_s * (Bv * G4);
#pragma unroll
            for (int nt = 0; nt < 2; nt++) {
                float2 lo = *reinterpret_cast<const float2*>(
                    gxt + (size_t)(bb + g) * G4 + gcol[nt]);
                float2 hi = *reinterpret_cast<const float2*>(
                    gxt + (size_t)(bb + g + 8) * G4 + gcol[nt]);
                gxv[nt][0] = lo.x; gxv[nt][1] = lo.y;
                gxv[nt][2] = hi.x; gxv[nt][3] = hi.y;
            }
        } else {
#pragma unroll
            for (int nt = 0; nt < 2; nt++)
#pragma unroll
                for (int q = 0; q < 4; q++) gxv[nt][q] = 0.f;
        }

        // ---- grid barrier: all blocks finished step t-1 ----
        if (t_s > 0) {
            __syncthreads();
            if (tid == 0) {
                unsigned target = bar_base + (unsigned)t_s;
                if (atomicAdd(&g_count, 1u) == NBLK - 1u) {
                    atomicExch(&g_count, 0u);
                    __threadfence();
                    atomicExch(&g_gen, target);
                } else {
                    while ((int)(atomicAdd(&g_gen, 0u) - target) < 0) { }
                }
                __threadfence();
            }
            __syncthreads();
        }

        // ---- stage h(t-1): pure copy of pre-split bf16 arrays ----
        if (t_s == 0) {
            for (int i = tid; i < 64 * HS; i += 512) {
                h_hi[i] = 0u; h_lo[i] = 0u;
            }
        } else {
            const uint4* ghi = reinterpret_cast<const uint4*>(g_hhi);
            const uint4* glo = reinterpret_cast<const uint4*>(g_hlo);
#pragma unroll 4
            for (int i = 0; i < 8; i++) {
                int f = tid + 512 * i;            // uint4 index < 4096
                int row = f >> 6, j = (f & 63) * 4;
                uint4 vh = __ldcg(ghi + f);
                uint4 vl = __ldcg(glo + f);
                *reinterpret_cast<uint4*>(&h_hi[row * HS + j]) = vh;
                *reinterpret_cast<uint4*>(&h_lo[row * HS + j]) = vl;
            }
        }
        __syncthreads();

        // ---- bf16-pair recurrent GEMM: K quarter, pure LDS->mma ----
        float acc[2][4];
#pragma unroll
        for (int nt = 0; nt < 2; nt++)
#pragma unroll
            for (int q = 0; q < 4; q++) acc[nt][q] = gxv[nt][q];

#pragma unroll
        for (int kt = 0; kt < 8; kt++) {
            int jb = jh + kt * 8;
            unsigned ah[4], al[4], bh[2][2], bl[2][2];
            ah[0] = h_hi[a0 + jb];     ah[1] = h_hi[a1 + jb];
            ah[2] = h_hi[a0 + jb + 4]; ah[3] = h_hi[a1 + jb + 4];
            al[0] = h_lo[a0 + jb];     al[1] = h_lo[a1 + jb];
            al[2] = h_lo[a0 + jb + 4]; al[3] = h_lo[a1 + jb + 4];
            bh[0][0] = w_hi[b0 + jb];  bh[0][1] = w_hi[b0 + jb + 4];
            bh[1][0] = w_hi[b1 + jb];  bh[1][1] = w_hi[b1 + jb + 4];
            bl[0][0] = w_lo[b0 + jb];  bl[0][1] = w_lo[b0 + jb + 4];
            bl[1][0] = w_lo[b1 + jb];  bl[1][1] = w_lo[b1 + jb + 4];
#pragma unroll
            for (int nt = 0; nt < 2; nt++) {
                mma_bf16(acc[nt], ah, bh[nt]);   // Whi*Hhi
                mma_bf16(acc[nt], al, bh[nt]);   // Whi*Hlo
                mma_bf16(acc[nt], ah, bl[nt]);   // Wlo*Hhi
            }
        }

        // ---- write split-K partials to ex[kq] ----
        {
            float* exs = ex + kq * EXSLAB;
#pragma unroll
            for (int nt = 0; nt < 2; nt++) {
                int c = nt * 8 + 2 * t;
                exs[c * 68 + bb + g]           = acc[nt][0];
                exs[(c + 1) * 68 + bb + g]     = acc[nt][1];
                exs[c * 68 + bb + g + 8]       = acc[nt][2];
                exs[(c + 1) * 68 + bb + g + 8] = acc[nt][3];
            }
        }
        __syncthreads();

        // ---- fused 4-way reduce + LSTM update + pre-split h for t+1 ----
        if (tid < 256) {
            float gate[4];
#pragma unroll
            for (int gg4 = 0; gg4 < 4; gg4++) {
                int c = gg4 * 4 + u_e;
                float s = ex[c * 68 + b_e];
#pragma unroll
                for (int sk = 1; sk < 4; sk++)
                    s += ex[sk * EXSLAB + c * 68 + b_e];
                gate[gg4] = s;
            }
            float si = 1.f / (1.f + expf(-gate[0]));
            float sf = 1.f / (1.f + expf(-gate[1]));
            float tg = tanhf(gate[2]);
            float so = 1.f / (1.f + expf(-gate[3]));
            float cc = sf * cpv + si * tg;
            cpv = cc;
            float hh = so * tanhf(cc);
            size_t o = (size_t)t_s * Bv * Hv + (size_t)b_e * Hv + u0 + u_e;
            __stcg(hs_out + o, hh);
            __stcg(cs_out + o, cc);
            // pre-split h for the next step's consumers
            unsigned short hi16 = bf16_of(hh);
            float fhi = __uint_as_float(((unsigned)hi16) << 16);
            unsigned short lo16 = bf16_of(hh - fhi);
            int idx = b_e * Hv + u0 + u_e;
            g_hhi[idx] = hi16;
            g_hlo[idx] = lo16;
        }

        if (t_s < Sv - 1) __threadfence();
    }
}

// ===========================================================================
// Launch
// ===========================================================================
extern "C" void kernel_launch(void* const* d_in, const int* in_sizes, int n_in,
                              void* d_out, int out_size)
{
    const float* seq  = (const float*)d_in[0];
    const float* w_ih = (const float*)d_in[1];
    const float* w_hh = (const float*)d_in[2];
    const float* b_ih = (const float*)d_in[3];
    const float* b_hh = (const float*)d_in[4];
    float* out = (float*)d_out;

    const int smem_p2 = SM2_WORDS * (int)sizeof(unsigned);   // 183808 B
    cudaFuncSetAttribute(lstm_rec_kernel,
                         cudaFuncAttributeMaxDynamicSharedMemorySize, smem_p2);

    dim3 g1(G4 / 128, (Sv * Bv) / 128);   // (16, 256)
    gemm_x_tf32<<<g1, 256>>>(seq, w_ih, b_ih, b_hh);
    lstm_rec_kernel<<<NBLK, 512, smem_p2>>>(w_hh, out);
}